// round 16
// baseline (speedup 1.0000x reference)
#include <cuda_runtime.h>
#include <cuda_bf16.h>

// CrossNetwork closed form, single fused kernel:
//   x_i = alpha_i * x0 + beta_i,  beta_i = sum_{j<i} b_j  (row-independent)
//   s_i = alpha_i * (x0 . w_i) + c_i,   c_i = beta_i . w_i  (per-CTA precomputed scalar)
//   alpha_{i+1} = alpha_i + s_i
//   out = alpha_4 * x0 + Bsum,   Bsum = sum_l b_l  (per-CTA precomputed, in smem)
// Each CTA stages w into smem and derives c[], Bsum itself (w/b are 32KB, L2-hot),
// then warps process rows: 4 simultaneous dots, scalar recurrence, one FMA stream.
// x read from HBM once, out written once.

#define D 1024
#define D4 (D / 4)
#define LAYERS 4
#define V4_PER_LANE 8     // 1024 / 32 lanes / 4
#define NTHREADS 256
#define NWARPS (NTHREADS / 32)

__global__ __launch_bounds__(NTHREADS, 3)
void cross_fused_kernel(const float* __restrict__ x,
                        const float* __restrict__ w,
                        const float* __restrict__ b,
                        float* __restrict__ out,
                        int rows, int total_warps)
{
    __shared__ float4 sW[LAYERS][D4];   // 16 KB: w, layer-major, conflict-free
    __shared__ float4 sB[D4];           //  4 KB: Bsum
    __shared__ float  sRed[3][NWARPS];  // c reduction scratch

    const int tid  = threadIdx.x;
    const int lane = tid & 31;
    const int wid  = tid >> 5;

    // ---- stage w into smem (4 float4 per thread) ----
    const float4* w4 = reinterpret_cast<const float4*>(w);
#pragma unroll
    for (int k = 0; k < LAYERS; k++)
        (&sW[0][0])[tid + k * NTHREADS] = w4[tid + k * NTHREADS];

    // ---- per-CTA precompute: Bsum -> sB, partial c1..c3 ----
    const float4* b4 = reinterpret_cast<const float4*>(b);
    {
        const float4 b0 = b4[tid];
        const float4 b1 = b4[tid + D4];
        const float4 b2 = b4[tid + 2 * D4];
        const float4 b3 = b4[tid + 3 * D4];
        // prefix sums (component-wise)
        float4 p1, p2, p3, p4;
        p1 = b0;
        p2.x = p1.x + b1.x; p2.y = p1.y + b1.y; p2.z = p1.z + b1.z; p2.w = p1.w + b1.w;
        p3.x = p2.x + b2.x; p3.y = p2.y + b2.y; p3.z = p2.z + b2.z; p3.w = p2.w + b2.w;
        p4.x = p3.x + b3.x; p4.y = p3.y + b3.y; p4.z = p3.z + b3.z; p4.w = p3.w + b3.w;
        sB[tid] = p4;

        const float4 w1v = w4[tid + D4];
        const float4 w2v = w4[tid + 2 * D4];
        const float4 w3v = w4[tid + 3 * D4];
        float c1p = 0.f, c2p = 0.f, c3p = 0.f;
        c1p = fmaf(p1.x, w1v.x, c1p); c1p = fmaf(p1.y, w1v.y, c1p);
        c1p = fmaf(p1.z, w1v.z, c1p); c1p = fmaf(p1.w, w1v.w, c1p);
        c2p = fmaf(p2.x, w2v.x, c2p); c2p = fmaf(p2.y, w2v.y, c2p);
        c2p = fmaf(p2.z, w2v.z, c2p); c2p = fmaf(p2.w, w2v.w, c2p);
        c3p = fmaf(p3.x, w3v.x, c3p); c3p = fmaf(p3.y, w3v.y, c3p);
        c3p = fmaf(p3.z, w3v.z, c3p); c3p = fmaf(p3.w, w3v.w, c3p);

        // warp reduce
#pragma unroll
        for (int off = 16; off > 0; off >>= 1) {
            c1p += __shfl_xor_sync(0xFFFFFFFFu, c1p, off);
            c2p += __shfl_xor_sync(0xFFFFFFFFu, c2p, off);
            c3p += __shfl_xor_sync(0xFFFFFFFFu, c3p, off);
        }
        if (lane == 0) {
            sRed[0][wid] = c1p; sRed[1][wid] = c2p; sRed[2][wid] = c3p;
        }
    }
    __syncthreads();

    // every thread sums the 8 warp partials (redundant, cheap, no 2nd barrier)
    float c1 = 0.f, c2 = 0.f, c3 = 0.f;
#pragma unroll
    for (int k = 0; k < NWARPS; k++) {
        c1 += sRed[0][k]; c2 += sRed[1][k]; c3 += sRed[2][k];
    }

    // ---- row loop: one warp per row ----
    const int warp0 = blockIdx.x * NWARPS + wid;

    for (int row = warp0; row < rows; row += total_warps) {
        const float4* __restrict__ xrow =
            reinterpret_cast<const float4*>(x) + (size_t)row * D4;

        // front-batched x0 load: 8 independent LDG.128 -> MLP ~8
        float4 x0[V4_PER_LANE];
#pragma unroll
        for (int i = 0; i < V4_PER_LANE; i++)
            x0[i] = xrow[lane + 32 * i];

        // four simultaneous dots of x0 with w_l (w from smem, conflict-free)
        float d0 = 0.f, d1 = 0.f, d2 = 0.f, d3 = 0.f;
#pragma unroll
        for (int i = 0; i < V4_PER_LANE; i++) {
            const int j = lane + 32 * i;
            const float4 a = x0[i];
            const float4 w0v = sW[0][j];
            d0 = fmaf(a.x, w0v.x, d0); d0 = fmaf(a.y, w0v.y, d0);
            d0 = fmaf(a.z, w0v.z, d0); d0 = fmaf(a.w, w0v.w, d0);
            const float4 w1v = sW[1][j];
            d1 = fmaf(a.x, w1v.x, d1); d1 = fmaf(a.y, w1v.y, d1);
            d1 = fmaf(a.z, w1v.z, d1); d1 = fmaf(a.w, w1v.w, d1);
            const float4 w2v = sW[2][j];
            d2 = fmaf(a.x, w2v.x, d2); d2 = fmaf(a.y, w2v.y, d2);
            d2 = fmaf(a.z, w2v.z, d2); d2 = fmaf(a.w, w2v.w, d2);
            const float4 w3v = sW[3][j];
            d3 = fmaf(a.x, w3v.x, d3); d3 = fmaf(a.y, w3v.y, d3);
            d3 = fmaf(a.z, w3v.z, d3); d3 = fmaf(a.w, w3v.w, d3);
        }

        // butterfly-reduce the four dots (independent chains overlap)
#pragma unroll
        for (int off = 16; off > 0; off >>= 1) {
            d0 += __shfl_xor_sync(0xFFFFFFFFu, d0, off);
            d1 += __shfl_xor_sync(0xFFFFFFFFu, d1, off);
            d2 += __shfl_xor_sync(0xFFFFFFFFu, d2, off);
            d3 += __shfl_xor_sync(0xFFFFFFFFu, d3, off);
        }

        // scalar recurrence: alpha_{i+1} = alpha_i + alpha_i*d_i + c_i  (c_0 = 0)
        float alpha = 1.0f;
        alpha += alpha * d0;
        alpha += fmaf(alpha, d1, c1);
        alpha += fmaf(alpha, d2, c2);
        alpha += fmaf(alpha, d3, c3);

        // out = alpha * x0 + Bsum
        float4* __restrict__ orow =
            reinterpret_cast<float4*>(out) + (size_t)row * D4;
#pragma unroll
        for (int i = 0; i < V4_PER_LANE; i++) {
            const int j = lane + 32 * i;
            const float4 a = x0[i];
            const float4 bs = sB[j];
            float4 o;
            o.x = fmaf(alpha, a.x, bs.x);
            o.y = fmaf(alpha, a.y, bs.y);
            o.z = fmaf(alpha, a.z, bs.z);
            o.w = fmaf(alpha, a.w, bs.w);
            orow[j] = o;
        }
    }
}

extern "C" void kernel_launch(void* const* d_in, const int* in_sizes, int n_in,
                              void* d_out, int out_size)
{
    const float* x = (const float*)d_in[0];   // [B, 1024]
    const float* w = (const float*)d_in[1];   // [4, 1024]
    const float* b = (const float*)d_in[2];   // [4, 1024]
    float* out = (float*)d_out;

    const int rows = in_sizes[0] / D;         // 16384

    const int blocks = 444;                   // 148 SMs x 3 CTAs -> single wave
    const int total_warps = blocks * NWARPS;  // 3552 warps, 4-5 rows each
    cross_fused_kernel<<<blocks, NTHREADS>>>(x, w, b, out, rows, total_warps);
}